// round 5
// baseline (speedup 1.0000x reference)
#include <cuda_runtime.h>
#include <cstdint>

#define BB 256
#define NN 512
#define FF 128
#define HH 128
#define K1 256
#define K2 128
#define NT (BB*NN)
#define EPER (NN*16)
#define EMAX (BB*EPER)

// ---------------- device scratch ----------------
__device__ float g_h[(size_t)NT*HH];        // x@W1
__device__ float g_hr[(size_t)NT*HH];       // relu(gcn1)
__device__ int   g_deg[NT];                 // self-clean
__device__ int   g_offs[NT];
__device__ int   g_cur[NT];
__device__ int   g_csr[EMAX];
__device__ float g_dinv1[NT];
__device__ float g_dinv2[NT];
__device__ float g_s1[NT];
__device__ int   g_keep[NT];
__device__ int   g_idx1[BB*K1];
__device__ float g_hk[(size_t)BB*K1*HH];
__device__ float g_Akb[(size_t)BB*K1*K1];   // pooled adjacency counts (self-clean)
__device__ float g_A1[(size_t)BB*K1*K1];
__device__ float g_q1[BB*K1], g_sv1[BB*K1], g_rowA1[BB*K1];
__device__ float g_hw[(size_t)BB*K1*HH];
__device__ float g_h2[(size_t)BB*K1*HH];
__device__ float g_tmp2[(size_t)BB*K1*HH];
__device__ float g_s2[BB*K1];
__device__ int   g_idx2[BB*K2];
__device__ float g_h2k[(size_t)BB*K2*HH];
__device__ float g_A2[(size_t)BB*K2*K2];
__device__ float g_q2[BB*K2], g_sv2[BB*K2], g_rowA2[BB*K2];
__device__ float g_hw3[(size_t)BB*K2*HH];
__device__ float g_h3[(size_t)BB*K2*HH];

// ---------------- 3xTF32 mma.sync GEMM (with fused prescale + epilogue) ----------------

#define ASTRIDE 36
#define BSTRIDE 136
#define GEMM_SMEM ((2*128*ASTRIDE + 2*32*BSTRIDE) * 4)

__device__ __forceinline__ float tf32r(float a) {
    uint32_t u;
    asm("cvt.rna.tf32.f32 %0, %1;" : "=r"(u) : "f"(a));
    return __uint_as_float(u);
}

#define MMA_TF32(d, a, b0, b1) \
    asm volatile("mma.sync.aligned.m16n8k8.row.col.f32.tf32.tf32.f32 " \
        "{%0,%1,%2,%3}, {%4,%5,%6,%7}, {%8,%9}, {%0,%1,%2,%3};" \
        : "+f"((d)[0]), "+f"((d)[1]), "+f"((d)[2]), "+f"((d)[3]) \
        : "r"((a)[0]), "r"((a)[1]), "r"((a)[2]), "r"((a)[3]), "r"(b0), "r"(b1))

// C[M,128] = A[M,K] @ diag(bscale?) @ B[K,128]; optional fused GCN epilogue (emode 1).
__global__ __launch_bounds__(256) void k_gemm_mma(
    const float* __restrict__ A, const float* __restrict__ Bm, float* __restrict__ C,
    int M, int K, long long sA, long long sB, long long sC,
    const float* __restrict__ bscale, float badd,
    const float* __restrict__ erow, float eadd,
    const float* __restrict__ ebias, const float* __restrict__ emat, int emode)
{
    extern __shared__ float sm[];
    float* Ah = sm;
    float* Al = Ah + 128 * ASTRIDE;
    float* Bh = Al + 128 * ASTRIDE;
    float* Bl = Bh + 32 * BSTRIDE;

    const int z = blockIdx.z;
    const float* Ab = A + (size_t)z * sA + (size_t)blockIdx.y * 128 * K;
    const float* Bb = Bm + (size_t)z * sB;
    float* Cb = C + (size_t)z * sC + (size_t)blockIdx.y * 128 * 128;

    const int tid = threadIdx.x;
    const int wid = tid >> 5, lane = tid & 31;
    const int wm = (wid >> 2) * 64, wn = (wid & 3) * 32;
    const int r = lane >> 2, cc = lane & 3;

    float acc[4][4][4];
#pragma unroll
    for (int i = 0; i < 4; i++)
#pragma unroll
        for (int j = 0; j < 4; j++)
#pragma unroll
            for (int q = 0; q < 4; q++) acc[i][j][q] = 0.f;

    const int nchunks = K >> 5;
    for (int c = 0; c < nchunks; c++) {
        const int k0 = c << 5;
        // stage A chunk 128x32, split hi/lo
#pragma unroll
        for (int i = 0; i < 4; i++) {
            int idx = tid + i * 256;
            int m = idx >> 3, kq = idx & 7;
            float4 v = *(const float4*)&Ab[(size_t)m * K + k0 + kq * 4];
            float4 h, l;
            h.x = tf32r(v.x); l.x = tf32r(v.x - h.x);
            h.y = tf32r(v.y); l.y = tf32r(v.y - h.y);
            h.z = tf32r(v.z); l.z = tf32r(v.z - h.z);
            h.w = tf32r(v.w); l.w = tf32r(v.w - h.w);
            *(float4*)&Ah[m * ASTRIDE + kq * 4] = h;
            *(float4*)&Al[m * ASTRIDE + kq * 4] = l;
        }
        // stage B chunk 32x128, optional row prescale, split hi/lo
#pragma unroll
        for (int i = 0; i < 4; i++) {
            int idx = tid + i * 256;
            int k = idx >> 5, cq = idx & 31;
            float4 v = *(const float4*)&Bb[(size_t)(k0 + k) * 128 + cq * 4];
            if (bscale) {
                float scl = rsqrtf(fmaxf(bscale[(size_t)z * K + k0 + k] + badd, 1e-12f));
                v.x *= scl; v.y *= scl; v.z *= scl; v.w *= scl;
            }
            float4 h, l;
            h.x = tf32r(v.x); l.x = tf32r(v.x - h.x);
            h.y = tf32r(v.y); l.y = tf32r(v.y - h.y);
            h.z = tf32r(v.z); l.z = tf32r(v.z - h.z);
            h.w = tf32r(v.w); l.w = tf32r(v.w - h.w);
            *(float4*)&Bh[k * BSTRIDE + cq * 4] = h;
            *(float4*)&Bl[k * BSTRIDE + cq * 4] = l;
        }
        __syncthreads();

#pragma unroll
        for (int ks = 0; ks < 4; ks++) {
            const int kk = ks << 3;
            uint32_t ah[4][4], al[4][4];
#pragma unroll
            for (int fm = 0; fm < 4; fm++) {
                const float* pa = &Ah[(wm + fm * 16 + r) * ASTRIDE + kk + cc];
                const float* pl = &Al[(wm + fm * 16 + r) * ASTRIDE + kk + cc];
                ah[fm][0] = __float_as_uint(pa[0]);
                ah[fm][1] = __float_as_uint(pa[8 * ASTRIDE]);
                ah[fm][2] = __float_as_uint(pa[4]);
                ah[fm][3] = __float_as_uint(pa[8 * ASTRIDE + 4]);
                al[fm][0] = __float_as_uint(pl[0]);
                al[fm][1] = __float_as_uint(pl[8 * ASTRIDE]);
                al[fm][2] = __float_as_uint(pl[4]);
                al[fm][3] = __float_as_uint(pl[8 * ASTRIDE + 4]);
            }
#pragma unroll
            for (int fn = 0; fn < 4; fn++) {
                const int nb = wn + fn * 8 + r;
                const int kb = kk + cc;
                uint32_t b0h = __float_as_uint(Bh[kb * BSTRIDE + nb]);
                uint32_t b1h = __float_as_uint(Bh[(kb + 4) * BSTRIDE + nb]);
                uint32_t b0l = __float_as_uint(Bl[kb * BSTRIDE + nb]);
                uint32_t b1l = __float_as_uint(Bl[(kb + 4) * BSTRIDE + nb]);
#pragma unroll
                for (int fm = 0; fm < 4; fm++) {
                    MMA_TF32(acc[fm][fn], ah[fm], b0h, b1h);
                    MMA_TF32(acc[fm][fn], ah[fm], b0l, b1l);
                    MMA_TF32(acc[fm][fn], al[fm], b0h, b1h);
                }
            }
        }
        __syncthreads();
    }

    // epilogue
    if (emode == 0) {
#pragma unroll
        for (int fm = 0; fm < 4; fm++) {
            int m = wm + fm * 16 + r;
#pragma unroll
            for (int fn = 0; fn < 4; fn++) {
                int col = wn + fn * 8 + cc * 2;
                *(float2*)&Cb[(size_t)m * 128 + col] =
                    make_float2(acc[fm][fn][0], acc[fm][fn][1]);
                *(float2*)&Cb[(size_t)(m + 8) * 128 + col] =
                    make_float2(acc[fm][fn][2], acc[fm][fn][3]);
            }
        }
    } else {
        // GCN combine: out = relu(d*C + d^2*emat + bias), d = rsqrt(max(erow+eadd,eps))
        const float* ematb = emat + (size_t)z * sC + (size_t)blockIdx.y * 128 * 128;
        const float* erowb = erow + (size_t)z * M + blockIdx.y * 128;
#pragma unroll
        for (int fm = 0; fm < 4; fm++) {
            int m = wm + fm * 16 + r;
            float d0 = rsqrtf(fmaxf(erowb[m] + eadd, 1e-12f));
            float d1 = rsqrtf(fmaxf(erowb[m + 8] + eadd, 1e-12f));
#pragma unroll
            for (int fn = 0; fn < 4; fn++) {
                int col = wn + fn * 8 + cc * 2;
                float2 e0 = *(const float2*)&ematb[(size_t)m * 128 + col];
                float2 e1 = *(const float2*)&ematb[(size_t)(m + 8) * 128 + col];
                float2 bb = *(const float2*)&ebias[col];
                float2 o0, o1;
                o0.x = fmaxf(d0 * acc[fm][fn][0] + d0 * d0 * e0.x + bb.x, 0.f);
                o0.y = fmaxf(d0 * acc[fm][fn][1] + d0 * d0 * e0.y + bb.y, 0.f);
                o1.x = fmaxf(d1 * acc[fm][fn][2] + d1 * d1 * e1.x + bb.x, 0.f);
                o1.y = fmaxf(d1 * acc[fm][fn][3] + d1 * d1 * e1.y + bb.y, 0.f);
                *(float2*)&Cb[(size_t)m * 128 + col] = o0;
                *(float2*)&Cb[(size_t)(m + 8) * 128 + col] = o1;
            }
        }
    }
}

// ---------------- smem-cached per-graph aggregation ----------------
// grid = BB*2 (graph, feature-half); 256 threads; dynamic smem holds the
// graph's 512x64 feature block + CSR + offsets + dinv.
#define AGG_SMEM (NN*64*4 + EPER*4 + NN*4*3)

template<int PASS>
__global__ __launch_bounds__(256) void k_agg_s(
    const float* __restrict__ featg, const float* __restrict__ bias, float* __restrict__ outp)
{
    extern __shared__ float sm[];
    float* feat = sm;                         // [512][64]
    int* csr = (int*)(sm + NN * 64);          // [EPER]
    int* soff = csr + EPER;                   // [512]
    int* send = soff + NN;                    // [512]
    float* sdinv = (float*)(send + NN);       // [512]

    const int g = blockIdx.x >> 1, hf = blockIdx.x & 1;
    const int tid = threadIdx.x;
    const int gbase = g * NN;
    const float* fg = featg + (size_t)gbase * HH + hf * 64;

    // load features (coalesced 256B segments)
#pragma unroll
    for (int i = 0; i < 32; i++) {
        int idx = tid + i * 256;
        int s = idx >> 4, q = (idx & 15) * 4;
        *(float4*)&feat[s * 64 + q] = *(const float4*)&fg[(size_t)s * HH + q];
    }
    // load CSR
#pragma unroll
    for (int i = 0; i < 8; i++) {
        int j = tid + i * 256;
        ((int4*)csr)[j] = ((const int4*)(g_csr + (size_t)g * EPER))[j];
    }
    // offsets + dinv
#pragma unroll
    for (int i = 0; i < 2; i++) {
        int s = tid + i * 256;
        soff[s] = g_offs[gbase + s] - g * EPER;
        send[s] = g_cur[gbase + s] - g * EPER;
        sdinv[s] = (PASS == 1 ? g_dinv1 : g_dinv2)[gbase + s];
    }
    __syncthreads();

    const int wid = tid >> 5, lane = tid & 31;
    for (int n = wid; n < NN; n += 8) {
        int e0 = soff[n], e1 = send[n];
        float dd = sdinv[n];
        float ax = 0.f, ay = 0.f;
        for (int e = e0; e < e1; e++) {
            int s = csr[e] & (NN - 1);
            float cf = sdinv[s] * dd;
            float2 v = *(const float2*)&feat[s * 64 + lane * 2];
            ax += v.x * cf; ay += v.y * cf;
        }
        float2 hv = *(const float2*)&feat[n * 64 + lane * 2];
        if (PASS == 1) {
            float sc = dd * dd;
            float bx = bias[hf * 64 + lane * 2];
            float by = bias[hf * 64 + lane * 2 + 1];
            float2 o;
            o.x = fmaxf(ax + hv.x * sc + bx, 0.f);
            o.y = fmaxf(ay + hv.y * sc + by, 0.f);
            *(float2*)&outp[(size_t)(gbase + n) * HH + hf * 64 + lane * 2] = o;
        } else {
            float sv = fabsf(hv.x - ax) + fabsf(hv.y - ay);
#pragma unroll
            for (int o = 16; o > 0; o >>= 1) sv += __shfl_down_sync(0xffffffffu, sv, o);
            if (lane == 0) atomicAdd(&outp[gbase + n], sv);
        }
    }
}

// ---------------- other kernels ----------------

__global__ void k_deg(const int* __restrict__ dst, int E) {
    int e = blockIdx.x * blockDim.x + threadIdx.x;
    if (e < E) atomicAdd(&g_deg[dst[e]], 1);
}

__global__ void k_scan(int eper) {
    __shared__ int sh[NN];
    int g = blockIdx.x, i = threadIdx.x;
    int n = g * NN + i;
    int d = g_deg[n];
    g_deg[n] = 0;
    g_dinv1[n] = rsqrtf((float)d + 1.0f);
    g_dinv2[n] = d > 0 ? rsqrtf((float)d) : 0.0f;
    g_s1[n] = 0.f;                              // zero for pass-2 atomic accumulation
    sh[i] = d; __syncthreads();
#pragma unroll
    for (int off = 1; off < NN; off <<= 1) {
        int v = (i >= off) ? sh[i - off] : 0;
        __syncthreads();
        sh[i] += v;
        __syncthreads();
    }
    int o = g * eper + sh[i] - d;
    g_offs[n] = o;
    g_cur[n] = o;
}

__global__ void k_fill(const int* __restrict__ src, const int* __restrict__ dst, int E) {
    int e = blockIdx.x * blockDim.x + threadIdx.x;
    if (e >= E) return;
    int pos = atomicAdd(&g_cur[dst[e]], 1);
    g_csr[pos] = src[e];
}

__global__ void k_topk(const float* __restrict__ scores, int n, int k,
                       int* __restrict__ idx_out, int* __restrict__ keep)
{
    extern __shared__ float ss[];
    int g = blockIdx.x, i = threadIdx.x;
    float si = scores[(size_t)g * n + i];
    ss[i] = si;
    __syncthreads();
    int rank = 0;
    for (int j = 0; j < n; j++) {
        float sj = ss[j];
        rank += (sj > si) || (sj == si && j < i);
    }
    if (rank < k) idx_out[(size_t)g * k + rank] = i;
    if (keep) keep[(size_t)g * n + i] = (rank < k) ? rank : -1;
}

__global__ void k_gather(const float* __restrict__ src, const int* __restrict__ idx,
                         float* __restrict__ dst, int rowsPerG, int k)
{
    int w = (blockIdx.x * blockDim.x + threadIdx.x) >> 5;
    if (w >= BB * k) return;
    int lane = threadIdx.x & 31;
    int g = w / k;
    int i = idx[w];
    ((float4*)(dst + (size_t)w * HH))[lane] =
        ((const float4*)(src + ((size_t)g * rowsPerG + i) * HH))[lane];
}

__global__ void k_edgeAk(const int* __restrict__ src, const int* __restrict__ dst, int E) {
    int e = blockIdx.x * blockDim.x + threadIdx.x;
    if (e >= E) return;
    int s = src[e];
    int rs = g_keep[s];
    if (rs < 0) return;
    int d = dst[e];
    int rd = g_keep[d];
    if (rd < 0) return;
    int g = s >> 9;
    atomicAdd(&g_Akb[((size_t)g * K1 + rs) * K1 + rd], 1.0f);
}

__global__ void k_qs(const float* __restrict__ feat, const float* __restrict__ att,
                     float* __restrict__ q, float* __restrict__ s, int rows)
{
    int w = (blockIdx.x * blockDim.x + threadIdx.x) >> 5;
    if (w >= rows) return;
    int lane = threadIdx.x & 31;
    float4 h4 = ((const float4*)(feat + (size_t)w * HH))[lane];
    float4 a4 = ((const float4*)att)[lane];
    float4 b4 = ((const float4*)att)[32 + lane];
    float qd = h4.x*a4.x + h4.y*a4.y + h4.z*a4.z + h4.w*a4.w;
    float sd = h4.x*b4.x + h4.y*b4.y + h4.z*b4.z + h4.w*b4.w;
#pragma unroll
    for (int o = 16; o > 0; o >>= 1) {
        qd += __shfl_down_sync(0xffffffffu, qd, o);
        sd += __shfl_down_sync(0xffffffffu, sd, o);
    }
    if (lane == 0) { q[w] = qd; s[w] = sd; }
}

template <int KDIM, int MODE>
__global__ void k_struct() {
    int row = blockIdx.x;
    int g = row / KDIM;
    int j = threadIdx.x;
    __shared__ float red[KDIM];
    float qi = (MODE == 0 ? g_q1 : g_q2)[row];
    float sj = (MODE == 0 ? g_sv1 : g_sv2)[(size_t)g * KDIM + j];
    float v = qi + sj;
    v = v > 0.f ? v : 0.2f * v;
    red[j] = v; __syncthreads();
    for (int st = KDIM / 2; st > 0; st >>= 1) {
        if (j < st) red[j] = fmaxf(red[j], red[j + st]);
        __syncthreads();
    }
    float vmax = red[0]; __syncthreads();
    float e = __expf(v - vmax);
    red[j] = e; __syncthreads();
    for (int st = KDIM / 2; st > 0; st >>= 1) {
        if (j < st) red[j] += red[j + st];
        __syncthreads();
    }
    float esum = red[0]; __syncthreads();
    float ak;
    if (MODE == 0) {
        size_t off = (size_t)row * K1 + j;
        ak = g_Akb[off];
        g_Akb[off] = 0.f;
    } else {
        int ig = g_idx2[row];
        int jg = g_idx2[g * K2 + j];
        ak = g_A1[((size_t)g * K1 + ig) * K1 + jg];
    }
    (MODE == 0 ? g_A1 : g_A2)[(size_t)row * KDIM + j] = e / esum + ak;
    red[j] = ak; __syncthreads();
    for (int st = KDIM / 2; st > 0; st >>= 1) {
        if (j < st) red[j] += red[j + st];
        __syncthreads();
    }
    if (j == 0) (MODE == 0 ? g_rowA1 : g_rowA2)[row] = red[0];
}

__global__ void k_readout(const float* __restrict__ feat, int k, float* __restrict__ out, int accumulate) {
    int g = blockIdx.x, f = threadIdx.x;
    float mx = -1e30f, sm = 0.f;
    const float* p = feat + (size_t)g * k * HH + f;
    for (int n = 0; n < k; n++) {
        float v = p[(size_t)n * HH];
        mx = fmaxf(mx, v);
        sm += v;
    }
    float o0 = fmaxf(mx, 0.f);
    float o1 = fmaxf(sm / (float)k, 0.f);
    if (accumulate) { out[g * 256 + f] += o0; out[g * 256 + 128 + f] += o1; }
    else            { out[g * 256 + f]  = o0; out[g * 256 + 128 + f]  = o1; }
}

__global__ void k_score2(const float* __restrict__ h2, const float* __restrict__ tmp2,
                         const float* __restrict__ rowA, float* __restrict__ sc, int rows) {
    int w = (blockIdx.x * blockDim.x + threadIdx.x) >> 5;
    if (w >= rows) return;
    int lane = threadIdx.x & 31;
    float d = rsqrtf(fmaxf(rowA[w] + 1.0f, 1e-12f));
    size_t base = (size_t)w * HH + lane * 4;
    float4 hv = *(const float4*)&h2[base];
    float4 tv = *(const float4*)&tmp2[base];
    float s = fabsf(hv.x - d*tv.x) + fabsf(hv.y - d*tv.y) + fabsf(hv.z - d*tv.z) + fabsf(hv.w - d*tv.w);
#pragma unroll
    for (int o = 16; o > 0; o >>= 1) s += __shfl_down_sync(0xffffffffu, s, o);
    if (lane == 0) sc[w] = s;
}

// ---------------- host ----------------

static float* symf(const void* sym) {
    void* p = nullptr;
    cudaGetSymbolAddress(&p, sym);
    return (float*)p;
}
static int* symi(const void* sym) {
    void* p = nullptr;
    cudaGetSymbolAddress(&p, sym);
    return (int*)p;
}

extern "C" void kernel_launch(void* const* d_in, const int* in_sizes, int n_in,
                              void* d_out, int out_size)
{
    const float* x    = (const float*)d_in[0];
    const float* W1   = (const float*)d_in[1];
    const float* b1   = (const float*)d_in[2];
    const float* W2   = (const float*)d_in[3];
    const float* b2   = (const float*)d_in[4];
    const float* W3   = (const float*)d_in[5];
    const float* b3   = (const float*)d_in[6];
    const float* att1 = (const float*)d_in[7];
    const float* att2 = (const float*)d_in[8];
    const int* esrc   = (const int*)d_in[9];
    const int* edst   = (const int*)d_in[10];
    int E = in_sizes[9];
    int eper = E / BB;
    float* out = (float*)d_out;

    static int attr_set = 0;
    if (!attr_set) {
        cudaFuncSetAttribute(k_gemm_mma, cudaFuncAttributeMaxDynamicSharedMemorySize, GEMM_SMEM);
        cudaFuncSetAttribute(k_agg_s<1>, cudaFuncAttributeMaxDynamicSharedMemorySize, AGG_SMEM);
        cudaFuncSetAttribute(k_agg_s<2>, cudaFuncAttributeMaxDynamicSharedMemorySize, AGG_SMEM);
        attr_set = 1;
    }

    float* p_h    = symf(g_h);
    float* p_hr   = symf(g_hr);
    float* p_s1   = symf(g_s1);
    int*   p_idx1 = symi(g_idx1);
    int*   p_keep = symi(g_keep);
    float* p_hk   = symf(g_hk);
    float* p_A1   = symf(g_A1);
    float* p_q1   = symf(g_q1);
    float* p_sv1  = symf(g_sv1);
    float* p_rA1  = symf(g_rowA1);
    float* p_hw   = symf(g_hw);
    float* p_h2   = symf(g_h2);
    float* p_tmp2 = symf(g_tmp2);
    float* p_s2   = symf(g_s2);
    int*   p_idx2 = symi(g_idx2);
    float* p_h2k  = symf(g_h2k);
    float* p_A2   = symf(g_A2);
    float* p_q2   = symf(g_q2);
    float* p_sv2  = symf(g_sv2);
    float* p_rA2  = symf(g_rowA2);
    float* p_hw3  = symf(g_hw3);
    float* p_h3   = symf(g_h3);

    // ---- stage 1: CSR build + edge GCN + info score (smem-cached) ----
    k_deg<<<(E + 255) / 256, 256>>>(edst, E);
    k_gemm_mma<<<dim3(1, NT / 128, 1), 256, GEMM_SMEM>>>(x, W1, p_h, NT, FF, 0, 0, 0,
        nullptr, 0.f, nullptr, 0.f, nullptr, nullptr, 0);
    k_scan<<<BB, NN>>>(eper);
    k_fill<<<(E + 255) / 256, 256>>>(esrc, edst, E);
    k_agg_s<1><<<BB * 2, 256, AGG_SMEM>>>(p_h, b1, p_hr);
    k_agg_s<2><<<BB * 2, 256, AGG_SMEM>>>(p_hr, nullptr, p_s1);

    // ---- pool 1 ----
    k_topk<<<BB, NN, NN * sizeof(float)>>>(p_s1, NN, K1, p_idx1, p_keep);
    k_gather<<<(BB * K1 * 32 + 255) / 256, 256>>>(p_hr, p_idx1, p_hk, NN, K1);
    k_edgeAk<<<(E + 255) / 256, 256>>>(esrc, edst, E);
    k_qs<<<(BB * K1 * 32 + 255) / 256, 256>>>(p_hk, att1, p_q1, p_sv1, BB * K1);
    k_struct<K1, 0><<<BB * K1, K1>>>();
    k_readout<<<BB, 128>>>(p_hk, K1, out, 0);

    // ---- conv2 (dense GCN on A1; prescale + combine fused into GEMM) ----
    k_gemm_mma<<<dim3(1, K1 / 128, BB), 256, GEMM_SMEM>>>(p_hk, W2, p_hw, K1, HH,
        (long long)K1 * HH, 0, (long long)K1 * HH,
        nullptr, 0.f, nullptr, 0.f, nullptr, nullptr, 0);
    k_gemm_mma<<<dim3(1, K1 / 128, BB), 256, GEMM_SMEM>>>(p_A1, p_hw, p_h2, K1, K1,
        (long long)K1 * K1, (long long)K1 * HH, (long long)K1 * HH,
        p_rA1, 2.0f, p_rA1, 2.0f, b2, p_hw, 1);

    // ---- info score 2 (prescale fused) ----
    k_gemm_mma<<<dim3(1, K1 / 128, BB), 256, GEMM_SMEM>>>(p_A1, p_h2, p_tmp2, K1, K1,
        (long long)K1 * K1, (long long)K1 * HH, (long long)K1 * HH,
        p_rA1, 1.0f, nullptr, 0.f, nullptr, nullptr, 0);
    k_score2<<<(BB * K1 * 32 + 255) / 256, 256>>>(p_h2, p_tmp2, p_rA1, p_s2, BB * K1);

    // ---- pool 2 ----
    k_topk<<<BB, K1, K1 * sizeof(float)>>>(p_s2, K1, K2, p_idx2, nullptr);
    k_gather<<<(BB * K2 * 32 + 255) / 256, 256>>>(p_h2, p_idx2, p_h2k, K1, K2);
    k_qs<<<(BB * K2 * 32 + 255) / 256, 256>>>(p_h2k, att2, p_q2, p_sv2, BB * K2);
    k_struct<K2, 1><<<BB * K2, K2>>>();
    k_readout<<<BB, 128>>>(p_h2k, K2, out, 1);

    // ---- conv3 (prescale + combine fused) ----
    k_gemm_mma<<<dim3(1, K2 / 128, BB), 256, GEMM_SMEM>>>(p_h2k, W3, p_hw3, K2, HH,
        (long long)K2 * HH, 0, (long long)K2 * HH,
        nullptr, 0.f, nullptr, 0.f, nullptr, nullptr, 0);
    k_gemm_mma<<<dim3(1, K2 / 128, BB), 256, GEMM_SMEM>>>(p_A2, p_hw3, p_h3, K2, K2,
        (long long)K2 * K2, (long long)K2 * HH, (long long)K2 * HH,
        p_rA2, 2.0f, p_rA2, 2.0f, b3, p_hw3, 1);
    k_readout<<<BB, 128>>>(p_h3, K2, out, 1);
}